// round 7
// baseline (speedup 1.0000x reference)
#include <cuda_runtime.h>
#include <cstdint>

#define RELS 3
#define NMAX 50000
#define HD   256      // H = HF*AH
#define KIN  128      // in_feats

// ---------------- scratch (static device globals; no allocation) ----------------
__device__ float g_hd   [(size_t)NMAX * HD];          // 51.2 MB
__device__ float g_hw   [(size_t)RELS * NMAX * HD];   // 153.6 MB
__device__ float g_num  [(size_t)NMAX * RELS * HD];   // 153.6 MB (concat layout [N, 768])
__device__ float g_denom[(size_t)RELS * NMAX * 4];    // [r][n][head]
__device__ float g_rcp  [(size_t)NMAX * 12];          // [n][r*4+a] reciprocal of denom
__device__ float g_p1   [NMAX];
__device__ float g_p2   [NMAX];
__device__ float g_qs   [(size_t)RELS * NMAX * 4];
__device__ float g_qd   [(size_t)RELS * NMAX * 4];
__device__ float g_f1   [HD];
__device__ float g_f2   [HD];

// ---------------- helpers ----------------
__device__ __forceinline__ void red_add_v4(float* p, float x, float y, float z, float w) {
    asm volatile("red.global.add.v4.f32 [%0], {%1, %2, %3, %4};"
                 :: "l"(p), "f"(x), "f"(y), "f"(z), "f"(w) : "memory");
}

// ---------------- zero-init kernels ----------------
__global__ void zero_num_kernel(size_t n4) {
    size_t i = (size_t)blockIdx.x * blockDim.x + threadIdx.x;
    if (i < n4) reinterpret_cast<float4*>(g_num)[i] = make_float4(0.f, 0.f, 0.f, 0.f);
}
__global__ void zero_den_kernel(int n) {
    int i = blockIdx.x * blockDim.x + threadIdx.x;
    if (i < n) g_denom[i] = 0.f;
}

// ---------------- fW folding: f1 = fW[0:256]+fW[512:768], f2 = fW[256:512]-fW[512:768]
__global__ void prep_f_kernel(const float* __restrict__ fW) {
    int c = threadIdx.x;
    g_f1[c] = fW[c]       + fW[512 + c];
    g_f2[c] = fW[256 + c] - fW[512 + c];
}

// =====================================================================
// GEMM: C[M,N] = (scale ⊙ A)[M,K] @ B[K,N] + bias[N]
// 128x128x16 tile, 256 threads, 8x8 microtile, double-buffered smem with
// register prefetch of the next global tile.
// If SCALED: A row m, k-block kb (64-wide) is multiplied by
//            rowScale[m*12 + (k>>6)]  (softmax normalization folded in).
// Requires: N % 128 == 0, K % 16 == 0, rows 16B-aligned.
// =====================================================================
#define BM2 128
#define BN2 128
#define BK2 16

template <bool SCALED>
__global__ __launch_bounds__(256, 2) void gemm128_kernel(
    const float* __restrict__ A, const float* __restrict__ B,
    const float* __restrict__ bias, float* __restrict__ C,
    int M, int N, int K, const float* __restrict__ rowScale)
{
    __shared__ float As[2][BK2][BM2 + 4];
    __shared__ float Bs[2][BK2][BN2];

    const int tid = threadIdx.x;
    const int tx  = tid & 15;           // 0..15 -> 128 cols, 8 each
    const int ty  = tid >> 4;           // 0..15 -> 128 rows, 8 each
    const int bm  = blockIdx.y * BM2;
    const int bn  = blockIdx.x * BN2;

    // A tile: 128 rows x 16 k = 512 float4, 2 per thread
    const int ar0 = tid >> 2;            // 0..63
    const int ar1 = ar0 + 64;            // 64..127
    const int akq = (tid & 3) << 2;      // k offset 0,4,8,12
    // B tile: 16 rows x 128 cols = 512 float4, 2 per thread
    const int br0 = tid >> 5;            // 0..7
    const int br1 = br0 + 8;             // 8..15
    const int bc4 = (tid & 31) << 2;     // col offset 0..124

    const int gm0 = bm + ar0;
    const int gm1 = bm + ar1;

    float acc[8][8];
#pragma unroll
    for (int i = 0; i < 8; i++)
#pragma unroll
        for (int j = 0; j < 8; j++) acc[i][j] = 0.f;

    // ---- prologue: load stage 0 ----
    {
        float4 av0 = make_float4(0.f,0.f,0.f,0.f), av1 = av0;
        if (gm0 < M) {
            av0 = *reinterpret_cast<const float4*>(A + (size_t)gm0 * K + akq);
            if (SCALED) { float s = rowScale[gm0 * 12]; av0.x*=s; av0.y*=s; av0.z*=s; av0.w*=s; }
        }
        if (gm1 < M) {
            av1 = *reinterpret_cast<const float4*>(A + (size_t)gm1 * K + akq);
            if (SCALED) { float s = rowScale[gm1 * 12]; av1.x*=s; av1.y*=s; av1.z*=s; av1.w*=s; }
        }
        As[0][akq+0][ar0]=av0.x; As[0][akq+1][ar0]=av0.y; As[0][akq+2][ar0]=av0.z; As[0][akq+3][ar0]=av0.w;
        As[0][akq+0][ar1]=av1.x; As[0][akq+1][ar1]=av1.y; As[0][akq+2][ar1]=av1.z; As[0][akq+3][ar1]=av1.w;
        float4 bv0 = *reinterpret_cast<const float4*>(B + (size_t)br0 * N + bn + bc4);
        float4 bv1 = *reinterpret_cast<const float4*>(B + (size_t)br1 * N + bn + bc4);
        *reinterpret_cast<float4*>(&Bs[0][br0][bc4]) = bv0;
        *reinterpret_cast<float4*>(&Bs[0][br1][bc4]) = bv1;
    }
    __syncthreads();

    int stage = 0;
    for (int k0 = 0; k0 < K; k0 += BK2) {
        const bool more = (k0 + BK2) < K;
        float4 av0, av1, bv0, bv1;
        if (more) {
            const int kn = k0 + BK2;
            av0 = make_float4(0.f,0.f,0.f,0.f); av1 = av0;
            if (gm0 < M) {
                av0 = *reinterpret_cast<const float4*>(A + (size_t)gm0 * K + kn + akq);
                if (SCALED) { float s = rowScale[gm0 * 12 + (kn >> 6)]; av0.x*=s; av0.y*=s; av0.z*=s; av0.w*=s; }
            }
            if (gm1 < M) {
                av1 = *reinterpret_cast<const float4*>(A + (size_t)gm1 * K + kn + akq);
                if (SCALED) { float s = rowScale[gm1 * 12 + (kn >> 6)]; av1.x*=s; av1.y*=s; av1.z*=s; av1.w*=s; }
            }
            bv0 = *reinterpret_cast<const float4*>(B + (size_t)(kn + br0) * N + bn + bc4);
            bv1 = *reinterpret_cast<const float4*>(B + (size_t)(kn + br1) * N + bn + bc4);
        }

        // ---- compute on current stage ----
#pragma unroll
        for (int k = 0; k < BK2; k++) {
            float4 a0 = *reinterpret_cast<const float4*>(&As[stage][k][ty * 8]);
            float4 a1 = *reinterpret_cast<const float4*>(&As[stage][k][ty * 8 + 4]);
            float4 b0 = *reinterpret_cast<const float4*>(&Bs[stage][k][tx * 8]);
            float4 b1 = *reinterpret_cast<const float4*>(&Bs[stage][k][tx * 8 + 4]);
            float ra[8] = {a0.x,a0.y,a0.z,a0.w,a1.x,a1.y,a1.z,a1.w};
            float rb[8] = {b0.x,b0.y,b0.z,b0.w,b1.x,b1.y,b1.z,b1.w};
#pragma unroll
            for (int i = 0; i < 8; i++)
#pragma unroll
                for (int j = 0; j < 8; j++)
                    acc[i][j] = fmaf(ra[i], rb[j], acc[i][j]);
        }

        if (more) {
            const int nxt = stage ^ 1;
            As[nxt][akq+0][ar0]=av0.x; As[nxt][akq+1][ar0]=av0.y; As[nxt][akq+2][ar0]=av0.z; As[nxt][akq+3][ar0]=av0.w;
            As[nxt][akq+0][ar1]=av1.x; As[nxt][akq+1][ar1]=av1.y; As[nxt][akq+2][ar1]=av1.z; As[nxt][akq+3][ar1]=av1.w;
            *reinterpret_cast<float4*>(&Bs[nxt][br0][bc4]) = bv0;
            *reinterpret_cast<float4*>(&Bs[nxt][br1][bc4]) = bv1;
            __syncthreads();
        }
        stage ^= 1;
    }

    // ---- epilogue ----
    const int n0 = bn + tx * 8;
    float4 bb0 = *reinterpret_cast<const float4*>(bias + n0);
    float4 bb1 = *reinterpret_cast<const float4*>(bias + n0 + 4);
#pragma unroll
    for (int i = 0; i < 8; i++) {
        int m = bm + ty * 8 + i;
        if (m >= M) continue;
        float4 o0, o1;
        o0.x = acc[i][0] + bb0.x; o0.y = acc[i][1] + bb0.y;
        o0.z = acc[i][2] + bb0.z; o0.w = acc[i][3] + bb0.w;
        o1.x = acc[i][4] + bb1.x; o1.y = acc[i][5] + bb1.y;
        o1.z = acc[i][6] + bb1.z; o1.w = acc[i][7] + bb1.w;
        *reinterpret_cast<float4*>(C + (size_t)m * N + n0)     = o0;
        *reinterpret_cast<float4*>(C + (size_t)m * N + n0 + 4) = o1;
    }
}

// ---------------- per-node scalars: p1,p2 (from hd) and qs,qd per relation/head ----------------
__global__ void scalars_kernel(const float* __restrict__ aW, int N) {
    int warp = (blockIdx.x * blockDim.x + threadIdx.x) >> 5;
    int lane = threadIdx.x & 31;
    if (warp >= N) return;

    const float4* hdrow = reinterpret_cast<const float4*>(g_hd + (size_t)warp * HD);
    float s1 = 0.f, s2 = 0.f;
#pragma unroll
    for (int q = 0; q < 2; q++) {
        int c4 = lane * 2 + q;
        float4 v  = hdrow[c4];
        float4 f1 = reinterpret_cast<const float4*>(g_f1)[c4];
        float4 f2 = reinterpret_cast<const float4*>(g_f2)[c4];
        s1 += v.x * f1.x + v.y * f1.y + v.z * f1.z + v.w * f1.w;
        s2 += v.x * f2.x + v.y * f2.y + v.z * f2.z + v.w * f2.w;
    }
#pragma unroll
    for (int o = 16; o > 0; o >>= 1) {
        s1 += __shfl_xor_sync(0xFFFFFFFFu, s1, o);
        s2 += __shfl_xor_sync(0xFFFFFFFFu, s2, o);
    }
    if (lane == 0) { g_p1[warp] = s1; g_p2[warp] = s2; }

    int a   = lane >> 3;
    int sub = lane & 7;
#pragma unroll
    for (int r = 0; r < RELS; r++) {
        const float4* hwrow = reinterpret_cast<const float4*>(g_hw + ((size_t)r * N + warp) * HD);
        const float4* aw    = reinterpret_cast<const float4*>(aW + r * 128);
        float t1 = 0.f, t2 = 0.f;
#pragma unroll
        for (int q = 0; q < 2; q++) {
            int within = sub * 2 + q;
            float4 v  = hwrow[a * 16 + within];
            float4 w1 = aw[within];
            float4 w2 = aw[16 + within];
            t1 += v.x * w1.x + v.y * w1.y + v.z * w1.z + v.w * w1.w;
            t2 += v.x * w2.x + v.y * w2.y + v.z * w2.z + v.w * w2.w;
        }
#pragma unroll
        for (int o = 4; o > 0; o >>= 1) {
            t1 += __shfl_xor_sync(0xFFFFFFFFu, t1, o);
            t2 += __shfl_xor_sync(0xFFFFFFFFu, t2, o);
        }
        if (sub == 0) {
            g_qs[((size_t)r * N + warp) * 4 + a] = t1;
            g_qd[((size_t)r * N + warp) * 4 + a] = t2;
        }
    }
}

// ---------------- edge kernel: one warp per edge ----------------
__global__ __launch_bounds__(256) void edge_kernel(
    const int* __restrict__ src, const int* __restrict__ dst,
    int r, const float* __restrict__ fb, const float* __restrict__ abr,
    int E, int N)
{
    int warp = (blockIdx.x * blockDim.x + threadIdx.x) >> 5;
    int lane = threadIdx.x & 31;
    if (warp >= E) return;

    const int s = __ldg(src + warp);
    const int d = __ldg(dst + warp);

    float score = g_p1[s] + g_p2[d] + fb[0];
    float sgn = (score > 0.f) ? 1.f : ((score < 0.f) ? -1.f : 0.f);

    const float* qsr = g_qs + (size_t)r * N * 4;
    const float* qdr = g_qd + (size_t)r * N * 4;
    int a = lane >> 3;
    float x = sgn * qsr[s * 4 + a] + qdr[d * 4 + a] + abr[0];
    float alpha = (x > 0.f) ? x : 0.01f * x;
    float ex = expf(alpha);

    if ((lane & 7) == 0)
        atomicAdd(g_denom + ((size_t)r * N + d) * 4 + a, ex);

    float v = ex * sgn;
    const float4* hrow = reinterpret_cast<const float4*>(g_hw + ((size_t)r * N + s) * HD) + lane * 2;
    float4 h0 = hrow[0];
    float4 h1 = hrow[1];
    float* out = g_num + (size_t)d * (RELS * HD) + r * HD + lane * 8;
    red_add_v4(out,     v * h0.x, v * h0.y, v * h0.z, v * h0.w);
    red_add_v4(out + 4, v * h1.x, v * h1.y, v * h1.z, v * h1.w);
}

// ---------------- reciprocal table: g_rcp[n*12 + r*4 + a] = 1/denom (0 if empty) ----------------
__global__ void rcp_kernel(int N) {
    int i = blockIdx.x * blockDim.x + threadIdx.x;
    if (i >= N * 12) return;
    int n = i / 12;
    int c = i - n * 12;
    int r = c >> 2;
    int a = c & 3;
    float den = g_denom[((size_t)r * N + n) * 4 + a];
    g_rcp[i] = (den > 0.f) ? (1.f / den) : 0.f;
}

// ---------------- launch ----------------
extern "C" void kernel_launch(void* const* d_in, const int* in_sizes, int n_in,
                              void* d_out, int out_size)
{
    const float* h    = (const float*)d_in[0];
    const float* dW   = (const float*)d_in[1];
    const float* db   = (const float*)d_in[2];
    const float* fW   = (const float*)d_in[3];
    const float* fb   = (const float*)d_in[4];
    const float* wW   = (const float*)d_in[5];
    const float* wb   = (const float*)d_in[6];
    const float* aW   = (const float*)d_in[7];
    const float* ab   = (const float*)d_in[8];
    const float* linW = (const float*)d_in[9];
    const float* linb = (const float*)d_in[10];
    const int*   src  = (const int*)d_in[11];
    const int*   dst  = (const int*)d_in[12];

    const int N = in_sizes[0] / KIN;        // 50000
    const int E = in_sizes[11] / RELS;      // 300000

    float *p_hd, *p_hw, *p_num, *p_rcp;
    cudaGetSymbolAddress((void**)&p_hd,  g_hd);
    cudaGetSymbolAddress((void**)&p_hw,  g_hw);
    cudaGetSymbolAddress((void**)&p_num, g_num);
    cudaGetSymbolAddress((void**)&p_rcp, g_rcp);

    // zero accumulators
    {
        size_t n4 = (size_t)N * (RELS * HD) / 4;
        zero_num_kernel<<<(unsigned)((n4 + 255) / 256), 256>>>(n4);
        int nd = RELS * N * 4;
        zero_den_kernel<<<(nd + 255) / 256, 256>>>(nd);
    }

    prep_f_kernel<<<1, 256>>>(fW);

    dim3 ggrid(HD / BN2, (N + BM2 - 1) / BM2);   // (2, 391)
    // hd = h @ dW + db
    gemm128_kernel<false><<<ggrid, 256>>>(h, dW, db, p_hd, N, HD, KIN, nullptr);
    // hw_r = h @ wW[r] + wb[r]
    for (int r = 0; r < RELS; r++)
        gemm128_kernel<false><<<ggrid, 256>>>(h, wW + (size_t)r * KIN * HD, wb + r * HD,
                                              p_hw + (size_t)r * N * HD, N, HD, KIN, nullptr);

    // per-node scalars
    scalars_kernel<<<(N + 7) / 8, 256>>>(aW, N);

    // edge aggregation per relation
    for (int r = 0; r < RELS; r++)
        edge_kernel<<<(E + 7) / 8, 256>>>(src + (size_t)r * E, dst + (size_t)r * E,
                                          r, fb, ab + r, E, N);

    // reciprocal of softmax denominators (folded into final GEMM A-load)
    rcp_kernel<<<(N * 12 + 255) / 256, 256>>>(N);

    // out = (rcp ⊙ num) @ linW + linb
    gemm128_kernel<true><<<ggrid, 256>>>(p_num, linW, linb, (float*)d_out,
                                         N, HD, RELS * HD, p_rcp);
}

// round 8
// speedup vs baseline: 1.0386x; 1.0386x over previous
#include <cuda_runtime.h>
#include <cstdint>

#define RELS 3
#define NMAX 50000
#define HD   256      // H = HF*AH
#define KIN  128      // in_feats

// ---------------- scratch (static device globals; no allocation) ----------------
__device__ float g_hw   [(size_t)RELS * NMAX * HD];   // 153.6 MB
__device__ float g_num  [(size_t)NMAX * RELS * HD];   // 153.6 MB (concat layout [N, 768])
__device__ float g_denom[(size_t)RELS * NMAX * 4];    // [r][n][head]
__device__ float g_rcp  [(size_t)NMAX * 12];          // [n][r*4+a] reciprocal of denom
__device__ float g_p1   [NMAX];
__device__ float g_p2   [NMAX];
__device__ float g_qs   [(size_t)RELS * NMAX * 4];
__device__ float g_qd   [(size_t)RELS * NMAX * 4];
__device__ float g_U    [32 * KIN];                   // folded projection vectors [col][k]
__device__ float g_Uc   [32];                         // folded constants per col

// ---------------- helpers ----------------
__device__ __forceinline__ void red_add_v4(float* p, float x, float y, float z, float w) {
    asm volatile("red.global.add.v4.f32 [%0], {%1, %2, %3, %4};"
                 :: "l"(p), "f"(x), "f"(y), "f"(z), "f"(w) : "memory");
}

// ---------------- zero-init kernels ----------------
__global__ void zero_num_kernel(size_t n4) {
    size_t i = (size_t)blockIdx.x * blockDim.x + threadIdx.x;
    if (i < n4) reinterpret_cast<float4*>(g_num)[i] = make_float4(0.f, 0.f, 0.f, 0.f);
}
__global__ void zero_den_kernel(int n) {
    int i = blockIdx.x * blockDim.x + threadIdx.x;
    if (i < n) g_denom[i] = 0.f;
}

// =====================================================================
// Fold all per-node scalar projections into U[32][128]:
//   col 0 : dW @ (fW[0:256]+fW[512:768])          -> p1
//   col 1 : dW @ (fW[256:512]-fW[512:768])        -> p2
//   col 2+c   (c=r*4+a) : wW[r][:,a*64:+64] @ aW[r][0:64]    -> qs
//   col 14+c  (c=r*4+a) : wW[r][:,a*64:+64] @ aW[r][64:128]  -> qd
//   cols 26..31 : zero
// =====================================================================
__global__ void prep_U_kernel(const float* __restrict__ dW, const float* __restrict__ fW,
                              const float* __restrict__ wW, const float* __restrict__ aW)
{
    int col = blockIdx.x;     // 0..31
    int k   = threadIdx.x;    // 0..127
    float s = 0.f;
    if (col < 2) {
        const float* dwr = dW + (size_t)k * HD;
        for (int j = 0; j < HD; j++) {
            float f = (col == 0) ? (fW[j] + fW[512 + j]) : (fW[256 + j] - fW[512 + j]);
            s += dwr[j] * f;
        }
    } else if (col < 26) {
        int c = col - 2;
        int half = 0;
        if (c >= 12) { c -= 12; half = 1; }
        int r = c >> 2, a = c & 3;
        const float* wwr = wW + ((size_t)r * KIN + k) * HD + a * 64;
        const float* awr = aW + r * 128 + half * 64;
        for (int j = 0; j < 64; j++) s += wwr[j] * awr[j];
    }
    g_U[col * KIN + k] = s;
}

__global__ void prep_Uc_kernel(const float* __restrict__ db, const float* __restrict__ fW,
                               const float* __restrict__ wb, const float* __restrict__ aW)
{
    int col = threadIdx.x;    // 0..31
    float s = 0.f;
    if (col < 2) {
        for (int j = 0; j < HD; j++) {
            float f = (col == 0) ? (fW[j] + fW[512 + j]) : (fW[256 + j] - fW[512 + j]);
            s += db[j] * f;
        }
    } else if (col < 26) {
        int c = col - 2;
        int half = 0;
        if (c >= 12) { c -= 12; half = 1; }
        int r = c >> 2, a = c & 3;
        const float* wbr = wb + r * HD + a * 64;
        const float* awr = aW + r * 128 + half * 64;
        for (int j = 0; j < 64; j++) s += wbr[j] * awr[j];
    }
    g_Uc[col] = s;
}

// =====================================================================
// Node scalars from h directly: one warp per node, lane = column.
//   scal[n, col] = h[n,:] . U[col,:] + Uc[col]
// =====================================================================
__global__ __launch_bounds__(256) void node_scalars_kernel(const float* __restrict__ h, int N)
{
    __shared__ float sh[8][KIN];
    const int tid  = threadIdx.x;
    const int node0 = blockIdx.x * 8;

    // stage 8 rows of h: 256 float4 loads
    {
        int row = tid >> 5;
        int w4  = tid & 31;
        int n = node0 + row;
        float4 v = make_float4(0.f, 0.f, 0.f, 0.f);
        if (n < N) v = *reinterpret_cast<const float4*>(h + (size_t)n * KIN + w4 * 4);
        *reinterpret_cast<float4*>(&sh[row][w4 * 4]) = v;
    }
    __syncthreads();

    const int w    = tid >> 5;
    const int lane = tid & 31;
    const int n    = node0 + w;
    if (n >= N || lane >= 26) return;

    const float4* urow = reinterpret_cast<const float4*>(g_U + lane * KIN);
    const float4* hrow = reinterpret_cast<const float4*>(&sh[w][0]);
    float acc = 0.f;
#pragma unroll
    for (int q = 0; q < 32; q++) {
        float4 hv = hrow[q];   // broadcast within warp
        float4 uv = urow[q];
        acc += hv.x * uv.x + hv.y * uv.y + hv.z * uv.z + hv.w * uv.w;
    }
    acc += g_Uc[lane];

    if (lane == 0)      g_p1[n] = acc;
    else if (lane == 1) g_p2[n] = acc;
    else if (lane < 14) {
        int c = lane - 2, r = c >> 2, a = c & 3;
        g_qs[((size_t)r * N + n) * 4 + a] = acc;
    } else {
        int c = lane - 14, r = c >> 2, a = c & 3;
        g_qd[((size_t)r * N + n) * 4 + a] = acc;
    }
}

// =====================================================================
// Tiled fp32 GEMM (R6 proven config): C = (scale ⊙ A) @ B + bias
// BM=128, BN=64, BK=16, TM=8, TN=4, 256 threads.
// SCALED: A row m, k-block (64-wide) scaled by rowScale[m*12 + (k>>6)].
// =====================================================================
#define GBM 128
#define GBN 64
#define GBK 16
template <bool SCALED>
__global__ __launch_bounds__(256) void gemm_bias_kernel(
    const float* __restrict__ A, const float* __restrict__ B,
    const float* __restrict__ bias, float* __restrict__ C,
    int M, int N, int K, const float* __restrict__ rowScale)
{
    __shared__ float As[GBK][GBM + 4];
    __shared__ float Bs[GBK][GBN];

    const int tid = threadIdx.x;
    const int tx = tid & 15;
    const int ty = tid >> 4;
    const int block_m = blockIdx.y * GBM;
    const int block_n = blockIdx.x * GBN;

    float acc[8][4];
#pragma unroll
    for (int i = 0; i < 8; i++)
#pragma unroll
        for (int j = 0; j < 4; j++) acc[i][j] = 0.f;

    const int b_row = tid >> 4;
    const int b_col = (tid & 15) << 2;

    for (int k0 = 0; k0 < K; k0 += GBK) {
#pragma unroll
        for (int f = tid; f < (GBM * GBK) / 4; f += 256) {
            int row = f >> 2;
            int kq  = (f & 3) << 2;
            int gm  = block_m + row;
            float4 av = make_float4(0.f, 0.f, 0.f, 0.f);
            if (gm < M) {
                av = *reinterpret_cast<const float4*>(A + (size_t)gm * K + k0 + kq);
                if (SCALED) {
                    float s = __ldg(rowScale + gm * 12 + ((k0 + kq) >> 6));
                    av.x *= s; av.y *= s; av.z *= s; av.w *= s;
                }
            }
            As[kq + 0][row] = av.x;
            As[kq + 1][row] = av.y;
            As[kq + 2][row] = av.z;
            As[kq + 3][row] = av.w;
        }
        {
            float4 bv = *reinterpret_cast<const float4*>(B + (size_t)(k0 + b_row) * N + block_n + b_col);
            *reinterpret_cast<float4*>(&Bs[b_row][b_col]) = bv;
        }
        __syncthreads();

#pragma unroll
        for (int k = 0; k < GBK; k++) {
            float4 ra0 = *reinterpret_cast<const float4*>(&As[k][ty * 8]);
            float4 ra1 = *reinterpret_cast<const float4*>(&As[k][ty * 8 + 4]);
            float4 rb  = *reinterpret_cast<const float4*>(&Bs[k][tx * 4]);
            float ra[8] = {ra0.x, ra0.y, ra0.z, ra0.w, ra1.x, ra1.y, ra1.z, ra1.w};
            float rbv[4] = {rb.x, rb.y, rb.z, rb.w};
#pragma unroll
            for (int i = 0; i < 8; i++)
#pragma unroll
                for (int j = 0; j < 4; j++)
                    acc[i][j] = fmaf(ra[i], rbv[j], acc[i][j]);
        }
        __syncthreads();
    }

    int n = block_n + tx * 4;
    float4 bb = *reinterpret_cast<const float4*>(bias + n);
#pragma unroll
    for (int i = 0; i < 8; i++) {
        int m = block_m + ty * 8 + i;
        if (m >= M) continue;
        float4 o;
        o.x = acc[i][0] + bb.x;
        o.y = acc[i][1] + bb.y;
        o.z = acc[i][2] + bb.z;
        o.w = acc[i][3] + bb.w;
        *reinterpret_cast<float4*>(C + (size_t)m * N + n) = o;
    }
}

// ---------------- edge kernel: one warp per edge ----------------
__global__ __launch_bounds__(256) void edge_kernel(
    const int* __restrict__ src, const int* __restrict__ dst,
    int r, const float* __restrict__ fb, const float* __restrict__ abr,
    int E, int N)
{
    int warp = (blockIdx.x * blockDim.x + threadIdx.x) >> 5;
    int lane = threadIdx.x & 31;
    if (warp >= E) return;

    const int s = __ldg(src + warp);
    const int d = __ldg(dst + warp);

    float score = g_p1[s] + g_p2[d] + fb[0];
    float sgn = (score > 0.f) ? 1.f : ((score < 0.f) ? -1.f : 0.f);

    const float* qsr = g_qs + (size_t)r * N * 4;
    const float* qdr = g_qd + (size_t)r * N * 4;
    int a = lane >> 3;
    float x = sgn * qsr[s * 4 + a] + qdr[d * 4 + a] + abr[0];
    float alpha = (x > 0.f) ? x : 0.01f * x;
    float ex = expf(alpha);

    if ((lane & 7) == 0)
        atomicAdd(g_denom + ((size_t)r * N + d) * 4 + a, ex);

    float v = ex * sgn;
    const float4* hrow = reinterpret_cast<const float4*>(g_hw + ((size_t)r * N + s) * HD) + lane * 2;
    float4 h0 = hrow[0];
    float4 h1 = hrow[1];
    float* out = g_num + (size_t)d * (RELS * HD) + r * HD + lane * 8;
    red_add_v4(out,     v * h0.x, v * h0.y, v * h0.z, v * h0.w);
    red_add_v4(out + 4, v * h1.x, v * h1.y, v * h1.z, v * h1.w);
}

// ---------------- reciprocal table: g_rcp[n*12 + r*4 + a] ----------------
__global__ void rcp_kernel(int N) {
    int i = blockIdx.x * blockDim.x + threadIdx.x;
    if (i >= N * 12) return;
    int n = i / 12;
    int c = i - n * 12;
    int r = c >> 2;
    int a = c & 3;
    float den = g_denom[((size_t)r * N + n) * 4 + a];
    g_rcp[i] = (den > 0.f) ? (1.f / den) : 0.f;
}

// ---------------- launch ----------------
extern "C" void kernel_launch(void* const* d_in, const int* in_sizes, int n_in,
                              void* d_out, int out_size)
{
    const float* h    = (const float*)d_in[0];
    const float* dW   = (const float*)d_in[1];
    const float* db   = (const float*)d_in[2];
    const float* fW   = (const float*)d_in[3];
    const float* fb   = (const float*)d_in[4];
    const float* wW   = (const float*)d_in[5];
    const float* wb   = (const float*)d_in[6];
    const float* aW   = (const float*)d_in[7];
    const float* ab   = (const float*)d_in[8];
    const float* linW = (const float*)d_in[9];
    const float* linb = (const float*)d_in[10];
    const int*   src  = (const int*)d_in[11];
    const int*   dst  = (const int*)d_in[12];

    const int N = in_sizes[0] / KIN;        // 50000
    const int E = in_sizes[11] / RELS;      // 300000

    float *p_hw, *p_num, *p_rcp;
    cudaGetSymbolAddress((void**)&p_hw,  g_hw);
    cudaGetSymbolAddress((void**)&p_num, g_num);
    cudaGetSymbolAddress((void**)&p_rcp, g_rcp);

    // zero accumulators
    {
        size_t n4 = (size_t)N * (RELS * HD) / 4;
        zero_num_kernel<<<(unsigned)((n4 + 255) / 256), 256>>>(n4);
        int nd = RELS * N * 4;
        zero_den_kernel<<<(nd + 255) / 256, 256>>>(nd);
    }

    // folded projection vectors + constants
    prep_U_kernel<<<32, 128>>>(dW, fW, wW, aW);
    prep_Uc_kernel<<<1, 32>>>(db, fW, wb, aW);

    // hw_r = h @ wW[r] + wb[r]   (the only remaining K=128 GEMMs)
    dim3 ggrid(HD / GBN, (N + GBM - 1) / GBM);   // (4, 391)
    for (int r = 0; r < RELS; r++)
        gemm_bias_kernel<false><<<ggrid, 256>>>(h, wW + (size_t)r * KIN * HD, wb + r * HD,
                                                p_hw + (size_t)r * N * HD, N, HD, KIN, nullptr);

    // per-node scalars straight from h
    node_scalars_kernel<<<(N + 7) / 8, 256>>>(h, N);

    // edge aggregation per relation
    for (int r = 0; r < RELS; r++)
        edge_kernel<<<(E + 7) / 8, 256>>>(src + (size_t)r * E, dst + (size_t)r * E,
                                          r, fb, ab + r, E, N);

    // reciprocal of softmax denominators (folded into final GEMM A-load)
    rcp_kernel<<<(N * 12 + 255) / 256, 256>>>(N);

    // out = (rcp ⊙ num) @ linW + linb
    gemm_bias_kernel<true><<<ggrid, 256>>>(p_num, linW, linb, (float*)d_out,
                                           N, HD, RELS * HD, p_rcp);
}